// round 13
// baseline (speedup 1.0000x reference)
#include <cuda_runtime.h>

// ---------------- shapes ----------------
#define BATCH 128
#define H0 224
#define W0 224
#define PH 56           // pooled H after conv1+maxpool
#define PW 56
#define C1 16
#define C2 32
#define H2 28
#define W2 28
#define N1CNT (128*112*112)
#define N2CNT (128*28*28)
#define NSLOT 64
#define BN_EPS 1e-5f

typedef unsigned long long u64;

// ---------------- scratch ----------------
__device__ float g_mx[(size_t)BATCH * C1 * PH * PW];
__device__ float g_mn[(size_t)BATCH * C1 * PH * PW];
__device__ float g_y2[(size_t)BATCH * C2 * H2 * W2];
__device__ float g_part1[NSLOT][32];
__device__ float g_part2[NSLOT][64];
__device__ float g_bn1s[C1], g_bn1t[C1];
__device__ float g_bn2s[C2], g_bn2t[C2];

// ---------------- packed fp32x2 helpers ----------------
__device__ __forceinline__ void fma2(u64& d, u64 a, u64 b) {
    asm("fma.rn.f32x2 %0, %1, %2, %0;" : "+l"(d) : "l"(a), "l"(b));
}
__device__ __forceinline__ void add2(u64& d, u64 a) {
    asm("add.rn.f32x2 %0, %0, %1;" : "+l"(d) : "l"(a));
}
__device__ __forceinline__ u64 pack_dup(float v) {
    u64 r;
    asm("mov.b64 %0, {%1, %1};" : "=l"(r) : "f"(v));
    return r;
}
__device__ __forceinline__ u64 pack2(float lo, float hi) {
    u64 r;
    asm("mov.b64 %0, {%1, %2};" : "=l"(r) : "f"(lo), "f"(hi));
    return r;
}
__device__ __forceinline__ float2 unpack2(u64 v) {
    float2 f;
    asm("mov.b64 {%0, %1}, %2;" : "=f"(f.x), "=f"(f.y) : "l"(v));
    return f;
}

// ---------------- kernel 0 ----------------
__global__ void zero_kernel() {
    int t = blockIdx.x * blockDim.x + threadIdx.x;
    if (t < NSLOT * 32) ((float*)g_part1)[t] = 0.f;
    if (t < NSLOT * 64) ((float*)g_part2)[t] = 0.f;
}

// ---------------- kernel 1: conv1 + pool min/max + stats (unchanged from R11) ----------------
__global__ __launch_bounds__(256, 2) void conv1_kernel(
    const float* __restrict__ x, const float* __restrict__ w,
    const float* __restrict__ bias)
{
    __shared__ ulonglong2 ws[27][4];
    __shared__ float bs[C1];
    __shared__ float red[8][32];

    int t = threadIdx.x;
    for (int i = t; i < 27 * 8; i += 256) {
        int tap = i >> 3, p = i & 7;
        ((u64*)ws)[tap * 8 + p] = pack2(w[(2 * p) * 27 + tap], w[(2 * p + 1) * 27 + tap]);
    }
    if (t < C1) bs[t] = bias[t];
    __syncthreads();

    int tid = blockIdx.x * 256 + t;
    int b   = tid / (PH * PW);
    int rem = tid - b * (PH * PW);
    int pi  = rem / PW;
    int pj  = rem - pi * PW;

    const float* xb = x + (size_t)b * 3 * H0 * W0;

    u64 acc[4][8];
    #pragma unroll
    for (int p = 0; p < 4; p++)
        #pragma unroll
        for (int j = 0; j < 8; j++) acc[p][j] = 0ULL;

    int r0b = 4 * pi - 1;
    int c0b = 4 * pj - 1;

    #pragma unroll
    for (int ic = 0; ic < 3; ic++) {
        const float* xc = xb + (size_t)ic * H0 * W0;
        float row[5][5];
        #pragma unroll
        for (int rr = 0; rr < 5; rr++) {
            int r = r0b + rr;
            bool rok = (unsigned)r < (unsigned)H0;
            #pragma unroll
            for (int cc = 0; cc < 5; cc++) {
                int c = c0b + cc;
                bool cok = (unsigned)c < (unsigned)W0;
                row[rr][cc] = (rok && cok) ? xc[r * W0 + c] : 0.f;
            }
        }
        #pragma unroll
        for (int kh = 0; kh < 3; kh++) {
            #pragma unroll
            for (int kw = 0; kw < 3; kw++) {
                u64 v00 = pack_dup(row[kh][kw]);
                u64 v01 = pack_dup(row[kh][kw + 2]);
                u64 v10 = pack_dup(row[kh + 2][kw]);
                u64 v11 = pack_dup(row[kh + 2][kw + 2]);
                const ulonglong2* wp = ws[ic * 9 + kh * 3 + kw];
                #pragma unroll
                for (int j = 0; j < 4; j++) {
                    ulonglong2 wv = wp[j];
                    fma2(acc[0][2*j],   v00, wv.x); fma2(acc[0][2*j+1], v00, wv.y);
                    fma2(acc[1][2*j],   v01, wv.x); fma2(acc[1][2*j+1], v01, wv.y);
                    fma2(acc[2][2*j],   v10, wv.x); fma2(acc[2][2*j+1], v10, wv.y);
                    fma2(acc[3][2*j],   v11, wv.x); fma2(acc[3][2*j+1], v11, wv.y);
                }
            }
        }
    }

    int warp = t >> 5;
    #pragma unroll
    for (int p = 0; p < 8; p++) {
        float2 A0 = unpack2(acc[0][p]);
        float2 A1 = unpack2(acc[1][p]);
        float2 A2 = unpack2(acc[2][p]);
        float2 A3 = unpack2(acc[3][p]);
        #pragma unroll
        for (int h = 0; h < 2; h++) {
            int ch = 2 * p + h;
            float bv = bs[ch];
            float a0 = (h ? A0.y : A0.x) + bv;
            float a1 = (h ? A1.y : A1.x) + bv;
            float a2 = (h ? A2.y : A2.x) + bv;
            float a3 = (h ? A3.y : A3.x) + bv;
            float mx = fmaxf(fmaxf(a0, a1), fmaxf(a2, a3));
            float mn = fminf(fminf(a0, a1), fminf(a2, a3));
            size_t oidx = ((size_t)(b * C1 + ch) * PH + pi) * PW + pj;
            g_mx[oidx] = mx;
            g_mn[oidx] = mn;
            float s = (a0 + a1) + (a2 + a3);
            float q = fmaf(a0, a0, fmaf(a1, a1, fmaf(a2, a2, a3 * a3)));
            #pragma unroll
            for (int off = 16; off; off >>= 1) {
                s += __shfl_xor_sync(0xFFFFFFFFu, s, off);
                q += __shfl_xor_sync(0xFFFFFFFFu, q, off);
            }
            if ((t & 31) == 0) { red[warp][ch] = s; red[warp][16 + ch] = q; }
        }
    }
    __syncthreads();
    if (t < 32) {
        float s = 0.f;
        #pragma unroll
        for (int wv = 0; wv < 8; wv++) s += red[wv][t];
        atomicAdd(&g_part1[blockIdx.x & (NSLOT - 1)][t], s);
    }
}

// ---------------- kernel 2 ----------------
__global__ void bn1_stats_kernel(const float* __restrict__ gam, const float* __restrict__ bet) {
    int t = threadIdx.x;
    if (t < C1) {
        float s = 0.f, q = 0.f;
        for (int w = 0; w < NSLOT; w++) { s += g_part1[w][t]; q += g_part1[w][16 + t]; }
        float inv  = 1.f / (float)N1CNT;
        float mean = s * inv;
        float var  = q * inv - mean * mean;
        float sc   = gam[t] * rsqrtf(var + BN_EPS);
        g_bn1s[t] = sc;
        g_bn1t[t] = bet[t] - mean * sc;
    }
}

// ---------------- kernel 3: conv2, INPUT-CHANNEL SPLIT across thread halves ----------------
// 128 threads/block handle 64 pixel-pairs: thread t (g = t>>6) accumulates
// input channels 8g..8g+7 into full 32-o-channel packed accumulators for
// pixel-pair slot (t&63). Partials combined through shared memory with
// add.rn.f32x2, then the g==1 half runs the epilogue. No duplicated LDG,
// no duplicated weight-LDS-per-FMA; grid doubles to 784 -> 5 blocks/SM.
#define Q2 (W2/2)   // 14
__global__ __launch_bounds__(128, 5) void conv2_kernel(
    const float* __restrict__ w2, const float* __restrict__ b2)
{
    __shared__ u64 pw[C1 * 9][16];     // 18.4 KB packed weights
    __shared__ u64 cmb[32][64];        // 16 KB combine buffer, [acc j][slot]
    __shared__ float bs[C2];
    __shared__ float s1s[C1], t1s[C1];
    __shared__ float red[2][64];

    int t = threadIdx.x;
    for (int i = t; i < 144 * 16; i += 128) {
        int tap = i >> 4, p = i & 15;
        pw[tap][p] = pack2(w2[(2 * p) * 144 + tap], w2[(2 * p + 1) * 144 + tap]);
    }
    if (t < C2) bs[t] = b2[t];
    if (t < C1) { s1s[t] = g_bn1s[t]; t1s[t] = g_bn1t[t]; }
    __syncthreads();

    int g  = t >> 6;                  // input-channel group: c in [8g, 8g+8)
    int sl = t & 63;                  // pixel-pair slot within block
    int pix = blockIdx.x * 64 + sl;
    int b   = pix / (H2 * Q2);
    int rem = pix - b * (H2 * Q2);
    int h2  = rem / Q2;
    int q   = rem - h2 * Q2;

    u64 acc[2][16];
    #pragma unroll
    for (int px = 0; px < 2; px++)
        #pragma unroll
        for (int j = 0; j < 16; j++) acc[px][j] = 0ULL;

    int cb = 4 * q - 1;
    int rb = 2 * h2 - 1;

    #pragma unroll 1
    for (int c0 = 0; c0 < 8; c0++) {
        int c = 8 * g + c0;
        float sc = s1s[c], tc = t1s[c];
        const float* P = (sc >= 0.f) ? g_mx : g_mn;
        const float* Pb = P + (size_t)(b * C1 + c) * PH * PW;
        float buf[15];
        #pragma unroll
        for (int kh = 0; kh < 3; kh++) {
            int r = rb + kh;
            bool rok = (unsigned)r < (unsigned)PH;
            #pragma unroll
            for (int cc = 0; cc < 5; cc++) {
                int cp = cb + cc;
                bool inb = rok && ((unsigned)cp < (unsigned)PW);
                buf[kh * 5 + cc] = inb ? fmaxf(fmaf(sc, Pb[r * PW + cp], tc), 0.f) : 0.f;
            }
        }
        #pragma unroll
        for (int kh = 0; kh < 3; kh++) {
            #pragma unroll
            for (int kw = 0; kw < 3; kw++) {
                u64 v0 = pack_dup(buf[kh * 5 + kw]);
                u64 v1 = pack_dup(buf[kh * 5 + kw + 2]);
                const ulonglong2* wp = (const ulonglong2*)pw[c * 9 + kh * 3 + kw];
                #pragma unroll
                for (int j = 0; j < 8; j++) {
                    ulonglong2 wv = wp[j];
                    fma2(acc[0][2*j],   v0, wv.x); fma2(acc[0][2*j+1], v0, wv.y);
                    fma2(acc[1][2*j],   v1, wv.x); fma2(acc[1][2*j+1], v1, wv.y);
                }
            }
        }
    }

    // combine halves: g==0 publishes, g==1 accumulates + epilogue
    if (g == 0) {
        #pragma unroll
        for (int j = 0; j < 16; j++) {
            cmb[j][sl]      = acc[0][j];
            cmb[16 + j][sl] = acc[1][j];
        }
    }
    __syncthreads();
    if (g == 1) {
        #pragma unroll
        for (int j = 0; j < 16; j++) {
            add2(acc[0][j], cmb[j][sl]);
            add2(acc[1][j], cmb[16 + j][sl]);
        }
        int warp = (t >> 5) & 1;           // 0 or 1 within the g==1 half
        #pragma unroll
        for (int p = 0; p < 16; p++) {
            float2 Y0 = unpack2(acc[0][p]);
            float2 Y1 = unpack2(acc[1][p]);
            #pragma unroll
            for (int h = 0; h < 2; h++) {
                int o = 2 * p + h;
                float bv = bs[o];
                float y0 = (h ? Y0.y : Y0.x) + bv;
                float y1 = (h ? Y1.y : Y1.x) + bv;
                size_t base = ((size_t)(b * C2 + o) * H2 + h2) * W2 + 2 * q;
                g_y2[base]     = y0;
                g_y2[base + 1] = y1;
                float s = y0 + y1;
                float qq = fmaf(y0, y0, y1 * y1);
                #pragma unroll
                for (int off = 16; off; off >>= 1) {
                    s  += __shfl_xor_sync(0xFFFFFFFFu, s, off);
                    qq += __shfl_xor_sync(0xFFFFFFFFu, qq, off);
                }
                if ((t & 31) == 0) { red[warp][o] = s; red[warp][32 + o] = qq; }
            }
        }
    }
    __syncthreads();
    if (t < 64) {
        float s = red[0][t] + red[1][t];
        atomicAdd(&g_part2[blockIdx.x & (NSLOT - 1)][t], s);
    }
}

// ---------------- kernel 4 ----------------
__global__ void bn2_stats_kernel(const float* __restrict__ gam, const float* __restrict__ bet) {
    int t = threadIdx.x;
    if (t < C2) {
        float s = 0.f, q = 0.f;
        for (int w = 0; w < NSLOT; w++) { s += g_part2[w][t]; q += g_part2[w][32 + t]; }
        float inv  = 1.f / (float)N2CNT;
        float mean = s * inv;
        float var  = q * inv - mean * mean;
        float sc   = gam[t] * rsqrtf(var + BN_EPS);
        g_bn2s[t] = sc;
        g_bn2t[t] = bet[t] - mean * sc;
    }
}

// ---------------- kernel 5: BN2+ReLU + avg + fc + cos ----------------
__global__ __launch_bounds__(256) void final_kernel(
    const float* __restrict__ fcw, const float* __restrict__ fcb,
    float* __restrict__ out)
{
    __shared__ float s2[C2], t2[C2], fw[C2];
    __shared__ float red[8];
    int t = threadIdx.x;
    if (t < C2) {
        s2[t] = g_bn2s[t];
        t2[t] = g_bn2t[t];
        fw[t] = fcw[t] * (1.f / (float)(H2 * W2));
    }
    __syncthreads();

    int b = blockIdx.x;
    const float* Y = g_y2 + (size_t)b * C2 * H2 * W2;
    float a = 0.f;
    for (int idx = t; idx < C2 * H2 * W2; idx += 256) {
        int c = idx / (H2 * W2);
        float v = fmaxf(fmaf(s2[c], Y[idx], t2[c]), 0.f);
        a = fmaf(v, fw[c], a);
    }
    #pragma unroll
    for (int off = 16; off; off >>= 1)
        a += __shfl_xor_sync(0xFFFFFFFFu, a, off);
    if ((t & 31) == 0) red[t >> 5] = a;
    __syncthreads();
    if (t == 0) {
        float tot = 0.f;
        #pragma unroll
        for (int w = 0; w < 8; w++) tot += red[w];
        float logit = tot + fcb[0];
        float p = cosf(logit);
        out[2 * b]     = p;
        out[2 * b + 1] = 1.f - p;
    }
}

// ---------------- launch ----------------
extern "C" void kernel_launch(void* const* d_in, const int* in_sizes, int n_in,
                              void* d_out, int out_size)
{
    const float* x       = (const float*)d_in[0];
    const float* conv1_w = (const float*)d_in[1];
    const float* conv1_b = (const float*)d_in[2];
    const float* bn1_g   = (const float*)d_in[3];
    const float* bn1_b   = (const float*)d_in[4];
    const float* conv2_w = (const float*)d_in[5];
    const float* conv2_b = (const float*)d_in[6];
    const float* bn2_g   = (const float*)d_in[7];
    const float* bn2_b   = (const float*)d_in[8];
    const float* fc_w    = (const float*)d_in[9];
    const float* fc_b    = (const float*)d_in[10];
    float* out = (float*)d_out;

    zero_kernel<<<16, 256>>>();

    conv1_kernel<<<(BATCH * PH * PW) / 256, 256>>>(x, conv1_w, conv1_b);

    bn1_stats_kernel<<<1, 32>>>(bn1_g, bn1_b);

    // 784 blocks: 64 pixel-pairs x 2 input-channel groups per block
    conv2_kernel<<<(BATCH * H2 * Q2) / 64, 128>>>(conv2_w, conv2_b);

    bn2_stats_kernel<<<1, 32>>>(bn2_g, bn2_b);

    final_kernel<<<BATCH, 256>>>(fc_w, fc_b, out);
}

// round 17
// speedup vs baseline: 1.1692x; 1.1692x over previous
#include <cuda_runtime.h>

// ---------------- shapes ----------------
#define BATCH 128
#define H0 224
#define W0 224
#define PH 56           // pooled H after conv1+maxpool
#define PW 56
#define C1 16
#define C2 32
#define H2 28
#define W2 28
#define N1CNT (128*112*112)
#define N2CNT (128*28*28)
#define NSLOT 64
#define BN_EPS 1e-5f

typedef unsigned long long u64;
typedef unsigned int u32;

// ---------------- scratch ----------------
__device__ float g_mx[(size_t)BATCH * C1 * PH * PW];
__device__ float g_mn[(size_t)BATCH * C1 * PH * PW];
__device__ float g_y2[(size_t)BATCH * C2 * H2 * W2];
__device__ float g_part1[NSLOT][32];
__device__ float g_part2[NSLOT][64];
__device__ float g_bn1s[C1], g_bn1t[C1];
__device__ float g_bn2s[C2], g_bn2t[C2];

// ---------------- packed fp32x2 helpers ----------------
__device__ __forceinline__ void fma2(u64& d, u64 a, u64 b) {
    asm("fma.rn.f32x2 %0, %1, %2, %0;" : "+l"(d) : "l"(a), "l"(b));
}
__device__ __forceinline__ u64 pack_dup(float v) {
    u64 r;
    asm("mov.b64 %0, {%1, %1};" : "=l"(r) : "f"(v));
    return r;
}
__device__ __forceinline__ u64 pack2(float lo, float hi) {
    u64 r;
    asm("mov.b64 %0, {%1, %2};" : "=l"(r) : "f"(lo), "f"(hi));
    return r;
}
__device__ __forceinline__ float2 unpack2(u64 v) {
    float2 f;
    asm("mov.b64 {%0, %1}, %2;" : "=f"(f.x), "=f"(f.y) : "l"(v));
    return f;
}

// ---------------- tf32 mma helpers ----------------
__device__ __forceinline__ u32 to_tf32(float x) {
    u32 r;
    asm("cvt.rna.tf32.f32 %0, %1;" : "=r"(r) : "f"(x));
    return r;
}
__device__ __forceinline__ void mma_tf32(float d[4], u32 a0, u32 a1, u32 a2, u32 a3,
                                         u32 b0, u32 b1) {
    asm("mma.sync.aligned.m16n8k8.row.col.f32.tf32.tf32.f32 "
        "{%0,%1,%2,%3}, {%4,%5,%6,%7}, {%8,%9}, {%0,%1,%2,%3};"
        : "+f"(d[0]), "+f"(d[1]), "+f"(d[2]), "+f"(d[3])
        : "r"(a0), "r"(a1), "r"(a2), "r"(a3), "r"(b0), "r"(b1));
}

// ---------------- kernel 0 ----------------
__global__ void zero_kernel() {
    int t = blockIdx.x * blockDim.x + threadIdx.x;
    if (t < NSLOT * 32) ((float*)g_part1)[t] = 0.f;
    if (t < NSLOT * 64) ((float*)g_part2)[t] = 0.f;
}

// ---------------- kernel 1: conv1 + pool min/max + stats (R11 best, unchanged) ----------------
__global__ __launch_bounds__(256, 2) void conv1_kernel(
    const float* __restrict__ x, const float* __restrict__ w,
    const float* __restrict__ bias)
{
    __shared__ ulonglong2 ws[27][4];
    __shared__ float bs[C1];
    __shared__ float red[8][32];

    int t = threadIdx.x;
    for (int i = t; i < 27 * 8; i += 256) {
        int tap = i >> 3, p = i & 7;
        ((u64*)ws)[tap * 8 + p] = pack2(w[(2 * p) * 27 + tap], w[(2 * p + 1) * 27 + tap]);
    }
    if (t < C1) bs[t] = bias[t];
    __syncthreads();

    int tid = blockIdx.x * 256 + t;
    int b   = tid / (PH * PW);
    int rem = tid - b * (PH * PW);
    int pi  = rem / PW;
    int pj  = rem - pi * PW;

    const float* xb = x + (size_t)b * 3 * H0 * W0;

    u64 acc[4][8];
    #pragma unroll
    for (int p = 0; p < 4; p++)
        #pragma unroll
        for (int j = 0; j < 8; j++) acc[p][j] = 0ULL;

    int r0b = 4 * pi - 1;
    int c0b = 4 * pj - 1;

    #pragma unroll
    for (int ic = 0; ic < 3; ic++) {
        const float* xc = xb + (size_t)ic * H0 * W0;
        float row[5][5];
        #pragma unroll
        for (int rr = 0; rr < 5; rr++) {
            int r = r0b + rr;
            bool rok = (unsigned)r < (unsigned)H0;
            #pragma unroll
            for (int cc = 0; cc < 5; cc++) {
                int c = c0b + cc;
                bool cok = (unsigned)c < (unsigned)W0;
                row[rr][cc] = (rok && cok) ? xc[r * W0 + c] : 0.f;
            }
        }
        #pragma unroll
        for (int kh = 0; kh < 3; kh++) {
            #pragma unroll
            for (int kw = 0; kw < 3; kw++) {
                u64 v00 = pack_dup(row[kh][kw]);
                u64 v01 = pack_dup(row[kh][kw + 2]);
                u64 v10 = pack_dup(row[kh + 2][kw]);
                u64 v11 = pack_dup(row[kh + 2][kw + 2]);
                const ulonglong2* wp = ws[ic * 9 + kh * 3 + kw];
                #pragma unroll
                for (int j = 0; j < 4; j++) {
                    ulonglong2 wv = wp[j];
                    fma2(acc[0][2*j],   v00, wv.x); fma2(acc[0][2*j+1], v00, wv.y);
                    fma2(acc[1][2*j],   v01, wv.x); fma2(acc[1][2*j+1], v01, wv.y);
                    fma2(acc[2][2*j],   v10, wv.x); fma2(acc[2][2*j+1], v10, wv.y);
                    fma2(acc[3][2*j],   v11, wv.x); fma2(acc[3][2*j+1], v11, wv.y);
                }
            }
        }
    }

    int warp = t >> 5;
    #pragma unroll
    for (int p = 0; p < 8; p++) {
        float2 A0 = unpack2(acc[0][p]);
        float2 A1 = unpack2(acc[1][p]);
        float2 A2 = unpack2(acc[2][p]);
        float2 A3 = unpack2(acc[3][p]);
        #pragma unroll
        for (int h = 0; h < 2; h++) {
            int ch = 2 * p + h;
            float bv = bs[ch];
            float a0 = (h ? A0.y : A0.x) + bv;
            float a1 = (h ? A1.y : A1.x) + bv;
            float a2 = (h ? A2.y : A2.x) + bv;
            float a3 = (h ? A3.y : A3.x) + bv;
            float mx = fmaxf(fmaxf(a0, a1), fmaxf(a2, a3));
            float mn = fminf(fminf(a0, a1), fminf(a2, a3));
            size_t oidx = ((size_t)(b * C1 + ch) * PH + pi) * PW + pj;
            g_mx[oidx] = mx;
            g_mn[oidx] = mn;
            float s = (a0 + a1) + (a2 + a3);
            float q = fmaf(a0, a0, fmaf(a1, a1, fmaf(a2, a2, a3 * a3)));
            #pragma unroll
            for (int off = 16; off; off >>= 1) {
                s += __shfl_xor_sync(0xFFFFFFFFu, s, off);
                q += __shfl_xor_sync(0xFFFFFFFFu, q, off);
            }
            if ((t & 31) == 0) { red[warp][ch] = s; red[warp][16 + ch] = q; }
        }
    }
    __syncthreads();
    if (t < 32) {
        float s = 0.f;
        #pragma unroll
        for (int wv = 0; wv < 8; wv++) s += red[wv][t];
        atomicAdd(&g_part1[blockIdx.x & (NSLOT - 1)][t], s);
    }
}

// ---------------- kernel 2 ----------------
__global__ void bn1_stats_kernel(const float* __restrict__ gam, const float* __restrict__ bet) {
    int t = threadIdx.x;
    if (t < C1) {
        float s = 0.f, q = 0.f;
        for (int w = 0; w < NSLOT; w++) { s += g_part1[w][t]; q += g_part1[w][16 + t]; }
        float inv  = 1.f / (float)N1CNT;
        float mean = s * inv;
        float var  = q * inv - mean * mean;
        float sc   = gam[t] * rsqrtf(var + BN_EPS);
        g_bn1s[t] = sc;
        g_bn1t[t] = bet[t] - mean * sc;
    }
}

// ---------------- kernel 3: conv2 as tf32 implicit GEMM (mma.sync m16n8k8) ----------------
// Per block: one (batch b, row-group rg) tile = 4 output rows x 28 cols = 112 px.
// 7 warps, warp w owns 16 pixels. M=112, N=32, K=144 (k = tap*16 + c).
// BN1+ReLU applied while staging raw halo tile [16 c][9 r][57 cols] in smem;
// A fragments gathered from raw tile via offtab (no im2col materialization).
#define RAW_RSTR 57
#define RAW_CSTR (9 * RAW_RSTR)          // 513
#define RAW_SZ   (C1 * RAW_CSTR)         // 8208 floats
#define WB_KSTR  145                      // wB[n][k], padded stride
#define WB_SZ    (C2 * WB_KSTR)          // 4640 floats
#define SM2_FLOATS (RAW_SZ + WB_SZ + 144 + 128 + C2 + C1 + C1)
#define SM2_BYTES  (SM2_FLOATS * 4)

__global__ __launch_bounds__(224) void conv2_kernel(
    const float* __restrict__ w2, const float* __restrict__ b2)
{
    extern __shared__ float sm[];
    float* raw    = sm;                       // RAW_SZ
    float* wB     = sm + RAW_SZ;              // WB_SZ
    int*   offtab = (int*)(wB + WB_SZ);       // 144
    float* sred   = (float*)(offtab + 144);   // 128 (sum 0..63 unused half ok: [och]=sum,[64+och]=sumsq)
    float* bsS    = sred + 128;               // 32
    float* s1S    = bsS + C2;                 // 16
    float* t1S    = s1S + C1;                 // 16

    int t = threadIdx.x;
    int bx = blockIdx.x;
    int b  = bx / 7;
    int rg = bx - b * 7;                      // row group: h2 in [4rg, 4rg+4)

    // ---- stage BN consts, bias, weights, offset table ----
    if (t < C1) { s1S[t] = g_bn1s[t]; t1S[t] = g_bn1t[t]; }
    if (t < C2) bsS[t] = b2[t];
    if (t < 128) sred[t] = 0.f;
    if (t < 144) {
        int c = t & 15, tap = t >> 4;
        int kh = tap / 3, kw = tap - 3 * kh;
        offtab[t] = c * RAW_CSTR + kh * RAW_RSTR + kw;
    }
    for (int i = t; i < C2 * 144; i += 224) {
        int n = i / 144, k = i - n * 144;
        int c = k & 15, tap = k >> 4;
        wB[n * WB_KSTR + k] = __uint_as_float(to_tf32(w2[n * 144 + c * 9 + tap]));
    }
    __syncthreads();

    // ---- stage raw halo tile with BN1+ReLU (pool via min/max trick) ----
    for (int i = t; i < RAW_SZ; i += 224) {
        int c   = i / RAW_CSTR;
        int rem = i - c * RAW_CSTR;
        int rr  = rem / RAW_RSTR;
        int cc  = rem - rr * RAW_RSTR;
        int r   = 8 * rg - 1 + rr;            // global pooled row
        int col = cc - 1;                     // global pooled col
        float v = 0.f;
        if ((unsigned)r < (unsigned)PH && (unsigned)col < (unsigned)PW) {
            float sc = s1S[c], tc = t1S[c];
            const float* P = (sc >= 0.f) ? g_mx : g_mn;
            v = fmaxf(fmaf(sc, P[((size_t)(b * C1 + c) * PH + r) * PW + col], tc), 0.f);
        }
        raw[i] = __uint_as_float(to_tf32(v));
    }
    __syncthreads();

    // ---- mma mainloop ----
    int wid  = t >> 5;                        // 0..6
    int lane = t & 31;
    int g    = lane >> 2;                     // group id 0..7
    int tig  = lane & 3;                      // thread in group

    int px0 = wid * 16 + g;                   // < 112 always
    int px1 = px0 + 8;
    int lr0 = px0 / 28, w0 = px0 - 28 * lr0;
    int lr1 = px1 / 28, w1 = px1 - 28 * lr1;
    int base0 = lr0 * (2 * RAW_RSTR) + 2 * w0;
    int base1 = lr1 * (2 * RAW_RSTR) + 2 * w1;

    float acc[4][4];
    #pragma unroll
    for (int nt = 0; nt < 4; nt++)
        #pragma unroll
        for (int j = 0; j < 4; j++) acc[nt][j] = 0.f;

    #pragma unroll
    for (int kt = 0; kt < 18; kt++) {
        int k0 = kt * 8;
        int oA  = offtab[k0 + tig];
        int oA4 = offtab[k0 + tig + 4];
        u32 a0 = __float_as_uint(raw[base0 + oA]);
        u32 a1 = __float_as_uint(raw[base1 + oA]);
        u32 a2 = __float_as_uint(raw[base0 + oA4]);
        u32 a3 = __float_as_uint(raw[base1 + oA4]);
        #pragma unroll
        for (int nt = 0; nt < 4; nt++) {
            const float* wrow = wB + (nt * 8 + g) * WB_KSTR + k0 + tig;
            u32 b0 = __float_as_uint(wrow[0]);
            u32 b1 = __float_as_uint(wrow[4]);
            mma_tf32(acc[nt], a0, a1, a2, a3, b0, b1);
        }
    }

    // ---- epilogue: bias, store y2, stats ----
    int h20 = rg * 4 + lr0;
    int h21 = rg * 4 + lr1;
    #pragma unroll
    for (int nt = 0; nt < 4; nt++) {
        int och0 = nt * 8 + 2 * tig;
        int och1 = och0 + 1;
        float y00 = acc[nt][0] + bsS[och0];   // (px0, och0)
        float y01 = acc[nt][1] + bsS[och1];   // (px0, och1)
        float y10 = acc[nt][2] + bsS[och0];   // (px1, och0)
        float y11 = acc[nt][3] + bsS[och1];   // (px1, och1)
        g_y2[((size_t)(b * C2 + och0) * H2 + h20) * W2 + w0] = y00;
        g_y2[((size_t)(b * C2 + och1) * H2 + h20) * W2 + w0] = y01;
        g_y2[((size_t)(b * C2 + och0) * H2 + h21) * W2 + w1] = y10;
        g_y2[((size_t)(b * C2 + och1) * H2 + h21) * W2 + w1] = y11;
        float s0 = y00 + y10, q0 = fmaf(y00, y00, y10 * y10);
        float s1 = y01 + y11, q1 = fmaf(y01, y01, y11 * y11);
        #pragma unroll
        for (int off = 4; off < 32; off <<= 1) {      // reduce over g lanes
            s0 += __shfl_xor_sync(0xFFFFFFFFu, s0, off);
            q0 += __shfl_xor_sync(0xFFFFFFFFu, q0, off);
            s1 += __shfl_xor_sync(0xFFFFFFFFu, s1, off);
            q1 += __shfl_xor_sync(0xFFFFFFFFu, q1, off);
        }
        if (g == 0) {
            atomicAdd(&sred[och0], s0);
            atomicAdd(&sred[64 + och0], q0);
            atomicAdd(&sred[och1], s1);
            atomicAdd(&sred[64 + och1], q1);
        }
    }
    __syncthreads();
    if (t < 64) {
        float val = (t < 32) ? sred[t] : sred[t + 32];
        atomicAdd(&g_part2[bx & (NSLOT - 1)][t], val);
    }
}

// ---------------- kernel 4 ----------------
__global__ void bn2_stats_kernel(const float* __restrict__ gam, const float* __restrict__ bet) {
    int t = threadIdx.x;
    if (t < C2) {
        float s = 0.f, q = 0.f;
        for (int w = 0; w < NSLOT; w++) { s += g_part2[w][t]; q += g_part2[w][32 + t]; }
        float inv  = 1.f / (float)N2CNT;
        float mean = s * inv;
        float var  = q * inv - mean * mean;
        float sc   = gam[t] * rsqrtf(var + BN_EPS);
        g_bn2s[t] = sc;
        g_bn2t[t] = bet[t] - mean * sc;
    }
}

// ---------------- kernel 5: BN2+ReLU + avg + fc + cos ----------------
__global__ __launch_bounds__(256) void final_kernel(
    const float* __restrict__ fcw, const float* __restrict__ fcb,
    float* __restrict__ out)
{
    __shared__ float s2[C2], t2[C2], fw[C2];
    __shared__ float red[8];
    int t = threadIdx.x;
    if (t < C2) {
        s2[t] = g_bn2s[t];
        t2[t] = g_bn2t[t];
        fw[t] = fcw[t] * (1.f / (float)(H2 * W2));
    }
    __syncthreads();

    int b = blockIdx.x;
    const float* Y = g_y2 + (size_t)b * C2 * H2 * W2;
    float a = 0.f;
    for (int idx = t; idx < C2 * H2 * W2; idx += 256) {
        int c = idx / (H2 * W2);
        float v = fmaxf(fmaf(s2[c], Y[idx], t2[c]), 0.f);
        a = fmaf(v, fw[c], a);
    }
    #pragma unroll
    for (int off = 16; off; off >>= 1)
        a += __shfl_xor_sync(0xFFFFFFFFu, a, off);
    if ((t & 31) == 0) red[t >> 5] = a;
    __syncthreads();
    if (t == 0) {
        float tot = 0.f;
        #pragma unroll
        for (int w = 0; w < 8; w++) tot += red[w];
        float logit = tot + fcb[0];
        float p = cosf(logit);
        out[2 * b]     = p;
        out[2 * b + 1] = 1.f - p;
    }
}

// ---------------- launch ----------------
extern "C" void kernel_launch(void* const* d_in, const int* in_sizes, int n_in,
                              void* d_out, int out_size)
{
    const float* x       = (const float*)d_in[0];
    const float* conv1_w = (const float*)d_in[1];
    const float* conv1_b = (const float*)d_in[2];
    const float* bn1_g   = (const float*)d_in[3];
    const float* bn1_b   = (const float*)d_in[4];
    const float* conv2_w = (const float*)d_in[5];
    const float* conv2_b = (const float*)d_in[6];
    const float* bn2_g   = (const float*)d_in[7];
    const float* bn2_b   = (const float*)d_in[8];
    const float* fc_w    = (const float*)d_in[9];
    const float* fc_b    = (const float*)d_in[10];
    float* out = (float*)d_out;

    static bool attr_set = false;
    if (!attr_set) {
        cudaFuncSetAttribute(conv2_kernel,
                             cudaFuncAttributeMaxDynamicSharedMemorySize, SM2_BYTES);
        attr_set = true;
    }

    zero_kernel<<<16, 256>>>();

    conv1_kernel<<<(BATCH * PH * PW) / 256, 256>>>(x, conv1_w, conv1_b);

    bn1_stats_kernel<<<1, 32>>>(bn1_g, bn1_b);

    // 896 blocks: (batch, 4-row group) tiles, 224 threads (7 warps x 16 px)
    conv2_kernel<<<BATCH * 7, 224, SM2_BYTES>>>(conv2_w, conv2_b);

    bn2_stats_kernel<<<1, 32>>>(bn2_g, bn2_b);

    final_kernel<<<BATCH, 256>>>(fc_w, fc_b, out);
}